// round 1
// baseline (speedup 1.0000x reference)
#include <cuda_runtime.h>
#include <cstdint>

// Problem constants
#define BATCH   131072
#define TILE    64          // samples per block
#define NTHR    256

// SMEM layout (floats)
//   xs  : [128][65]                       8320
//   A   : reused region                   41312
//     embed : feat [64][132] (8448) + w [128][65] (8320)
//     qkv   : qkv [128][193] (24704) + in_w [64][193] (12352); out_w [64][65] at +24704
//     ff    : f1 [64][257] (16448) + f2 [256][65] (16640) + hbuf [32][257] (8224)
//     head  : h1 [128][65] (8320) + hbuf2 [64][65] (4160)
#define XS_FLOATS   (128*65)
#define A_FLOATS    (64*257 + 256*65 + 32*257)
#define SMEM_FLOATS (XS_FLOATS + A_FLOATS)
#define SMEM_BYTES  (SMEM_FLOATS * 4)

__device__ __forceinline__ void stage_w(float* dst, const float* src, int N, int K, int tid)
{
    // src: [N][K] row-major (global). dst: [K][N+1] (smem, transposed, padded).
    const int stride = N + 1;
    for (int idx = tid; idx < N * K; idx += NTHR) {
        int n = idx / K;
        int k = idx - n * K;
        dst[k * stride + n] = __ldg(src + idx);
    }
}

__device__ __forceinline__ void ln_row(float* r, const float* g, const float* b)
{
    float m = 0.f;
    #pragma unroll
    for (int c = 0; c < 64; ++c) m += r[c];
    m *= (1.0f / 64.0f);
    float v = 0.f;
    #pragma unroll
    for (int c = 0; c < 64; ++c) { float d = r[c] - m; v += d * d; }
    v *= (1.0f / 64.0f);
    float inv = rsqrtf(v + 1e-5f);
    #pragma unroll
    for (int c = 0; c < 64; ++c)
        r[c] = (r[c] - m) * inv * __ldg(g + c) + __ldg(b + c);
}

__global__ void __launch_bounds__(NTHR, 1)
TransformerRecSys_58806692217038_kernel(
    const int*   __restrict__ user_idx,
    const int*   __restrict__ item_idx,
    const float* __restrict__ user_features,
    const float* __restrict__ item_features,
    const float* __restrict__ user_table,
    const float* __restrict__ item_table,
    const float* __restrict__ upw,
    const float* __restrict__ upb,
    const float* __restrict__ ipw,
    const float* __restrict__ ipb,
    const float* __restrict__ pe,
    const float* __restrict__ in_w,
    const float* __restrict__ in_b,
    const float* __restrict__ out_w,
    const float* __restrict__ out_b,
    const float* __restrict__ ln1_g,
    const float* __restrict__ ln1_b,
    const float* __restrict__ ff1_w,
    const float* __restrict__ ff1_b,
    const float* __restrict__ ff2_w,
    const float* __restrict__ ff2_b,
    const float* __restrict__ ln2_g,
    const float* __restrict__ ln2_b,
    const float* __restrict__ h1_w,
    const float* __restrict__ h1_b,
    const float* __restrict__ h2_w,
    const float* __restrict__ h2_b,
    float*       __restrict__ out)
{
    extern __shared__ float sm[];
    float* xs = sm;                 // [128][65]  row = 2*sample_local + pos
    float* A  = sm + XS_FLOATS;

    __shared__ int sidx[128];       // [0:64) user idx, [64:128) item idx

    const int tid = threadIdx.x;
    const int tx  = tid & 31;
    const int ty  = tid >> 5;
    const int s0  = blockIdx.x << 6;

    if (tid < 64)       sidx[tid] = user_idx[s0 + tid];
    else if (tid < 128) sidx[tid] = item_idx[s0 + tid - 64];

    // ================= embeddings: x[2s+side] = table[idx] + feat @ W^T + b + pe =================
    {
        float* feat = A;               // [64][132]
        float* wst  = A + 64 * 132;    // [128][65]
        for (int side = 0; side < 2; ++side) {
            const float* fsrc = side ? item_features : user_features;
            const float* wsrc = side ? ipw : upw;
            const float* bsrc = side ? ipb : upb;
            const float* tbl  = side ? item_table : user_table;
            __syncthreads();   // sidx visible; feat/wst reuse safe
            const float4* src4 = reinterpret_cast<const float4*>(fsrc + (size_t)s0 * 128);
            for (int idx = tid; idx < 2048; idx += NTHR) {
                int s  = idx >> 5;
                int k4 = idx & 31;
                *reinterpret_cast<float4*>(feat + s * 132 + (k4 << 2)) = __ldg(src4 + idx);
            }
            stage_w(wst, wsrc, 64, 128, tid);
            __syncthreads();

            float acc[8][2];
            #pragma unroll
            for (int i = 0; i < 8; ++i) { acc[i][0] = 0.f; acc[i][1] = 0.f; }
            #pragma unroll 4
            for (int k = 0; k < 128; ++k) {
                float w0 = wst[k * 65 + tx];
                float w1 = wst[k * 65 + tx + 32];
                #pragma unroll
                for (int i = 0; i < 8; ++i) {
                    float xv = feat[(ty * 8 + i) * 132 + k];
                    acc[i][0] += xv * w0;
                    acc[i][1] += xv * w1;
                }
            }
            #pragma unroll
            for (int i = 0; i < 8; ++i) {
                int s   = ty * 8 + i;
                int row = 2 * s + side;
                size_t trow = (size_t)sidx[side * 64 + s] * 64;
                #pragma unroll
                for (int j = 0; j < 2; ++j) {
                    int n = tx + 32 * j;
                    xs[row * 65 + n] = acc[i][j] + __ldg(bsrc + n)
                                     + __ldg(tbl + trow + n) + __ldg(pe + side * 64 + n);
                }
            }
        }
    }
    __syncthreads();

    // ================= transformer layers =================
    float* qkv = A;                 // [128][193]  q:[0,64) k:[64,128) v:[128,192)
    float* wl  = A + 128 * 193;     // in_w [64][193], later out_w [64][65]

    for (int l = 0; l < 2; ++l) {
        // ---- qkv = x @ in_w^T + in_b ----
        stage_w(wl, in_w + l * 192 * 64, 192, 64, tid);
        __syncthreads();
        for (int rb = 0; rb < 128; rb += 64) {
            float acc[8][6];
            #pragma unroll
            for (int i = 0; i < 8; ++i)
                #pragma unroll
                for (int j = 0; j < 6; ++j) acc[i][j] = 0.f;
            #pragma unroll 4
            for (int k = 0; k < 64; ++k) {
                float wv[6];
                #pragma unroll
                for (int j = 0; j < 6; ++j) wv[j] = wl[k * 193 + tx + 32 * j];
                #pragma unroll
                for (int i = 0; i < 8; ++i) {
                    float xv = xs[(rb + ty * 8 + i) * 65 + k];
                    #pragma unroll
                    for (int j = 0; j < 6; ++j) acc[i][j] += xv * wv[j];
                }
            }
            const float* bb = in_b + l * 192;
            #pragma unroll
            for (int i = 0; i < 8; ++i)
                #pragma unroll
                for (int j = 0; j < 6; ++j) {
                    int n = tx + 32 * j;
                    qkv[(rb + ty * 8 + i) * 193 + n] = acc[i][j] + __ldg(bb + n);
                }
        }
        __syncthreads();

        // ---- attention (seq=2): one lane per (sample, head); ctx overwrites q slot ----
        {
            int sl = ((tid >> 5) << 3) + ((tid & 31) >> 2);   // sample_local 0..63
            int h  = tid & 3;                                  // head
            float* bp = qkv + (2 * sl) * 193 + h * 16;
            float s00 = 0.f, s01 = 0.f, s10 = 0.f, s11 = 0.f;
            #pragma unroll
            for (int d = 0; d < 16; ++d) {
                float q0 = bp[d],       q1 = bp[193 + d];
                float k0 = bp[64 + d],  k1 = bp[257 + d];
                s00 += q0 * k0; s01 += q0 * k1;
                s10 += q1 * k0; s11 += q1 * k1;
            }
            const float sc = 0.25f;   // 1/sqrt(16)
            s00 *= sc; s01 *= sc; s10 *= sc; s11 *= sc;
            float m0 = fmaxf(s00, s01), m1 = fmaxf(s10, s11);
            float e00 = expf(s00 - m0), e01 = expf(s01 - m0);
            float e10 = expf(s10 - m1), e11 = expf(s11 - m1);
            float i0 = 1.f / (e00 + e01), i1 = 1.f / (e10 + e11);
            float w00 = e00 * i0, w01 = e01 * i0;
            float w10 = e10 * i1, w11 = e11 * i1;
            #pragma unroll
            for (int d = 0; d < 16; ++d) {
                float v0 = bp[128 + d], v1 = bp[321 + d];
                bp[d]       = w00 * v0 + w01 * v1;
                bp[193 + d] = w10 * v0 + w11 * v1;
            }
        }
        // ---- out projection weights (reuse wl region; qkv/ctx untouched) ----
        stage_w(wl, out_w + l * 64 * 64, 64, 64, tid);
        __syncthreads();

        // ---- x += ctx @ out_w^T + out_b ----
        for (int rb = 0; rb < 128; rb += 64) {
            float acc[8][2];
            #pragma unroll
            for (int i = 0; i < 8; ++i) { acc[i][0] = 0.f; acc[i][1] = 0.f; }
            #pragma unroll 4
            for (int k = 0; k < 64; ++k) {
                float w0 = wl[k * 65 + tx];
                float w1 = wl[k * 65 + tx + 32];
                #pragma unroll
                for (int i = 0; i < 8; ++i) {
                    float xv = qkv[(rb + ty * 8 + i) * 193 + k];   // ctx in q slot
                    acc[i][0] += xv * w0;
                    acc[i][1] += xv * w1;
                }
            }
            #pragma unroll
            for (int i = 0; i < 8; ++i) {
                int row = rb + ty * 8 + i;
                #pragma unroll
                for (int j = 0; j < 2; ++j) {
                    int n = tx + 32 * j;
                    xs[row * 65 + n] += acc[i][j] + __ldg(out_b + l * 64 + n);
                }
            }
        }
        __syncthreads();
        if (tid < 128) ln_row(xs + tid * 65, ln1_g + l * 64, ln1_b + l * 64);
        __syncthreads();

        // ---- feed-forward: x += relu(x @ ff1^T + b1) @ ff2^T + b2 ----
        float* f1 = A;               // [64][257]
        float* f2 = A + 64 * 257;    // [256][65]
        float* hb = f2 + 256 * 65;   // [32][257]
        stage_w(f1, ff1_w + l * 256 * 64, 256, 64, tid);
        stage_w(f2, ff2_w + l * 64 * 256, 64, 256, tid);
        __syncthreads();

        for (int ch = 0; ch < 4; ++ch) {
            // pass 1: hidden = relu(x @ ff1^T + b1) for 32 rows
            float acc1[4][8];
            #pragma unroll
            for (int i = 0; i < 4; ++i)
                #pragma unroll
                for (int j = 0; j < 8; ++j) acc1[i][j] = 0.f;
            #pragma unroll 4
            for (int k = 0; k < 64; ++k) {
                float wv[8];
                #pragma unroll
                for (int j = 0; j < 8; ++j) wv[j] = f1[k * 257 + tx + 32 * j];
                #pragma unroll
                for (int i = 0; i < 4; ++i) {
                    float xv = xs[(ch * 32 + ty * 4 + i) * 65 + k];
                    #pragma unroll
                    for (int j = 0; j < 8; ++j) acc1[i][j] += xv * wv[j];
                }
            }
            #pragma unroll
            for (int i = 0; i < 4; ++i)
                #pragma unroll
                for (int j = 0; j < 8; ++j) {
                    int n = tx + 32 * j;
                    hb[(ty * 4 + i) * 257 + n] =
                        fmaxf(acc1[i][j] + __ldg(ff1_b + l * 256 + n), 0.f);
                }
            __syncthreads();

            // pass 2: x += hidden @ ff2^T + b2
            float acc2[4][2];
            #pragma unroll
            for (int i = 0; i < 4; ++i) { acc2[i][0] = 0.f; acc2[i][1] = 0.f; }
            #pragma unroll 4
            for (int k = 0; k < 256; ++k) {
                float w0 = f2[k * 65 + tx];
                float w1 = f2[k * 65 + tx + 32];
                #pragma unroll
                for (int i = 0; i < 4; ++i) {
                    float xv = hb[(ty * 4 + i) * 257 + k];
                    acc2[i][0] += xv * w0;
                    acc2[i][1] += xv * w1;
                }
            }
            #pragma unroll
            for (int i = 0; i < 4; ++i) {
                int row = ch * 32 + ty * 4 + i;
                #pragma unroll
                for (int j = 0; j < 2; ++j) {
                    int n = tx + 32 * j;
                    xs[row * 65 + n] += acc2[i][j] + __ldg(ff2_b + l * 64 + n);
                }
            }
            __syncthreads();
        }
        if (tid < 128) ln_row(xs + tid * 65, ln2_g + l * 64, ln2_b + l * 64);
        __syncthreads();
    }

    // ================= head: pred = relu(concat @ h1^T + b1) @ h2^T + b2 =================
    {
        float* h1  = A;              // [128][65]
        float* hb2 = A + 128 * 65;   // [64][65]
        stage_w(h1, h1_w, 64, 128, tid);
        __syncthreads();

        float acc[8][2];
        #pragma unroll
        for (int i = 0; i < 8; ++i) { acc[i][0] = 0.f; acc[i][1] = 0.f; }
        #pragma unroll 4
        for (int k = 0; k < 64; ++k) {           // first half of concat: pos 0 row
            float w0 = h1[k * 65 + tx];
            float w1 = h1[k * 65 + tx + 32];
            #pragma unroll
            for (int i = 0; i < 8; ++i) {
                float xv = xs[(2 * (ty * 8 + i)) * 65 + k];
                acc[i][0] += xv * w0;
                acc[i][1] += xv * w1;
            }
        }
        #pragma unroll 4
        for (int k = 64; k < 128; ++k) {         // second half: pos 1 row
            float w0 = h1[k * 65 + tx];
            float w1 = h1[k * 65 + tx + 32];
            #pragma unroll
            for (int i = 0; i < 8; ++i) {
                float xv = xs[(2 * (ty * 8 + i) + 1) * 65 + (k - 64)];
                acc[i][0] += xv * w0;
                acc[i][1] += xv * w1;
            }
        }
        #pragma unroll
        for (int i = 0; i < 8; ++i)
            #pragma unroll
            for (int j = 0; j < 2; ++j) {
                int n = tx + 32 * j;
                hb2[(ty * 8 + i) * 65 + n] = fmaxf(acc[i][j] + __ldg(h1_b + n), 0.f);
            }
        __syncthreads();

        if (tid < 64) {
            float p = __ldg(h2_b);
            #pragma unroll 8
            for (int n = 0; n < 64; ++n)
                p += hb2[tid * 65 + n] * __ldg(h2_w + n);
            out[s0 + tid] = p;
        }
    }
}

extern "C" void kernel_launch(void* const* d_in, const int* in_sizes, int n_in,
                              void* d_out, int out_size)
{
    const int*   user_idx      = (const int*)  d_in[0];
    const int*   item_idx      = (const int*)  d_in[1];
    const float* user_features = (const float*)d_in[2];
    const float* item_features = (const float*)d_in[3];
    const float* user_table    = (const float*)d_in[4];
    const float* item_table    = (const float*)d_in[5];
    const float* upw           = (const float*)d_in[6];
    const float* upb           = (const float*)d_in[7];
    const float* ipw           = (const float*)d_in[8];
    const float* ipb           = (const float*)d_in[9];
    const float* pe            = (const float*)d_in[10];
    const float* in_w          = (const float*)d_in[11];
    const float* in_b          = (const float*)d_in[12];
    const float* out_w         = (const float*)d_in[13];
    const float* out_b         = (const float*)d_in[14];
    const float* ln1_g         = (const float*)d_in[15];
    const float* ln1_b         = (const float*)d_in[16];
    const float* ff1_w         = (const float*)d_in[17];
    const float* ff1_b         = (const float*)d_in[18];
    const float* ff2_w         = (const float*)d_in[19];
    const float* ff2_b         = (const float*)d_in[20];
    const float* ln2_g         = (const float*)d_in[21];
    const float* ln2_b         = (const float*)d_in[22];
    const float* h1_w          = (const float*)d_in[23];
    const float* h1_b          = (const float*)d_in[24];
    const float* h2_w          = (const float*)d_in[25];
    const float* h2_b          = (const float*)d_in[26];
    float* out = (float*)d_out;

    const int B = in_sizes[0];           // user_idx element count = batch
    cudaFuncSetAttribute(TransformerRecSys_58806692217038_kernel,
                         cudaFuncAttributeMaxDynamicSharedMemorySize, SMEM_BYTES);

    TransformerRecSys_58806692217038_kernel<<<B / TILE, NTHR, SMEM_BYTES>>>(
        user_idx, item_idx, user_features, item_features, user_table, item_table,
        upw, upb, ipw, ipb, pe, in_w, in_b, out_w, out_b, ln1_g, ln1_b,
        ff1_w, ff1_b, ff2_w, ff2_b, ln2_g, ln2_b, h1_w, h1_b, h2_w, h2_b, out);
}

// round 2
// speedup vs baseline: 1.0516x; 1.0516x over previous
#include <cuda_runtime.h>
#include <cstdint>

// Problem constants
#define BATCH   131072
#define TILE    64          // samples per block
#define NTHR    256

// SMEM layout (floats)
//   xs  : [128][65]                       8320
//   A   : reused region                   41312
//     embed : feat [64][132] (8448) + w [128][65] (8320)
//     qkv   : qkv [128][193] (24704) + in_w [64][193] (12352); out_w [64][65] at +24704
//     ff    : f1 [64][257] (16448) + f2 [256][65] (16640) + hbuf [32][257] (8224)
//     head  : h1 [128][65] (8320) + hbuf2 [64][65] (4160)
#define XS_FLOATS   (128*65)
#define A_FLOATS    (64*257 + 256*65 + 32*257)
#define SMEM_FLOATS (XS_FLOATS + A_FLOATS)
#define SMEM_BYTES  (SMEM_FLOATS * 4)

__device__ __forceinline__ void stage_w(float* dst, const float* src, int N, int K, int tid)
{
    // src: [N][K] row-major (global). dst: [K][N+1] (smem, transposed, padded).
    const int stride = N + 1;
    for (int idx = tid; idx < N * K; idx += NTHR) {
        int n = idx / K;
        int k = idx - n * K;
        dst[k * stride + n] = __ldg(src + idx);
    }
}

__device__ __forceinline__ void ln_row(float* r, const float* g, const float* b)
{
    float m = 0.f;
    #pragma unroll
    for (int c = 0; c < 64; ++c) m += r[c];
    m *= (1.0f / 64.0f);
    float v = 0.f;
    #pragma unroll
    for (int c = 0; c < 64; ++c) { float d = r[c] - m; v += d * d; }
    v *= (1.0f / 64.0f);
    float inv = rsqrtf(v + 1e-5f);
    #pragma unroll
    for (int c = 0; c < 64; ++c)
        r[c] = (r[c] - m) * inv * __ldg(g + c) + __ldg(b + c);
}

__global__ void __launch_bounds__(NTHR, 1)
TransformerRecSys_58806692217038_kernel(
    const int*   __restrict__ user_idx,
    const int*   __restrict__ item_idx,
    const float* __restrict__ user_features,
    const float* __restrict__ item_features,
    const float* __restrict__ user_table,
    const float* __restrict__ item_table,
    const float* __restrict__ upw,
    const float* __restrict__ upb,
    const float* __restrict__ ipw,
    const float* __restrict__ ipb,
    const float* __restrict__ pe,
    const float* __restrict__ in_w,
    const float* __restrict__ in_b,
    const float* __restrict__ out_w,
    const float* __restrict__ out_b,
    const float* __restrict__ ln1_g,
    const float* __restrict__ ln1_b,
    const float* __restrict__ ff1_w,
    const float* __restrict__ ff1_b,
    const float* __restrict__ ff2_w,
    const float* __restrict__ ff2_b,
    const float* __restrict__ ln2_g,
    const float* __restrict__ ln2_b,
    const float* __restrict__ h1_w,
    const float* __restrict__ h1_b,
    const float* __restrict__ h2_w,
    const float* __restrict__ h2_b,
    float*       __restrict__ out)
{
    extern __shared__ float sm[];
    float* xs = sm;                 // [128][65]  row = 2*sample_local + pos
    float* A  = sm + XS_FLOATS;

    __shared__ int sidx[128];       // [0:64) user idx, [64:128) item idx

    const int tid = threadIdx.x;
    const int tx  = tid & 31;
    const int ty  = tid >> 5;
    const int s0  = blockIdx.x << 6;

    if (tid < 64)       sidx[tid] = user_idx[s0 + tid];
    else if (tid < 128) sidx[tid] = item_idx[s0 + tid - 64];

    // ================= embeddings: x[2s+side] = table[idx] + feat @ W^T + b + pe =================
    {
        float* feat = A;               // [64][132]
        float* wst  = A + 64 * 132;    // [128][65]
        for (int side = 0; side < 2; ++side) {
            const float* fsrc = side ? item_features : user_features;
            const float* wsrc = side ? ipw : upw;
            const float* bsrc = side ? ipb : upb;
            const float* tbl  = side ? item_table : user_table;
            __syncthreads();   // sidx visible; feat/wst reuse safe
            const float4* src4 = reinterpret_cast<const float4*>(fsrc + (size_t)s0 * 128);
            for (int idx = tid; idx < 2048; idx += NTHR) {
                int s  = idx >> 5;
                int k4 = idx & 31;
                *reinterpret_cast<float4*>(feat + s * 132 + (k4 << 2)) = __ldg(src4 + idx);
            }
            stage_w(wst, wsrc, 64, 128, tid);
            __syncthreads();

            float acc[8][2];
            #pragma unroll
            for (int i = 0; i < 8; ++i) { acc[i][0] = 0.f; acc[i][1] = 0.f; }
            #pragma unroll 4
            for (int k = 0; k < 128; ++k) {
                float w0 = wst[k * 65 + tx];
                float w1 = wst[k * 65 + tx + 32];
                #pragma unroll
                for (int i = 0; i < 8; ++i) {
                    float xv = feat[(ty * 8 + i) * 132 + k];
                    acc[i][0] += xv * w0;
                    acc[i][1] += xv * w1;
                }
            }
            #pragma unroll
            for (int i = 0; i < 8; ++i) {
                int s   = ty * 8 + i;
                int row = 2 * s + side;
                size_t trow = (size_t)sidx[side * 64 + s] * 64;
                #pragma unroll
                for (int j = 0; j < 2; ++j) {
                    int n = tx + 32 * j;
                    xs[row * 65 + n] = acc[i][j] + __ldg(bsrc + n)
                                     + __ldg(tbl + trow + n) + __ldg(pe + side * 64 + n);
                }
            }
        }
    }
    __syncthreads();

    // ================= transformer layers =================
    float* qkv = A;                 // [128][193]  q:[0,64) k:[64,128) v:[128,192)
    float* wl  = A + 128 * 193;     // in_w [64][193], later out_w [64][65]

    for (int l = 0; l < 2; ++l) {
        // ---- qkv = x @ in_w^T + in_b ----
        stage_w(wl, in_w + l * 192 * 64, 192, 64, tid);
        __syncthreads();
        for (int rb = 0; rb < 128; rb += 64) {
            float acc[8][6];
            #pragma unroll
            for (int i = 0; i < 8; ++i)
                #pragma unroll
                for (int j = 0; j < 6; ++j) acc[i][j] = 0.f;
            #pragma unroll 4
            for (int k = 0; k < 64; ++k) {
                float wv[6];
                #pragma unroll
                for (int j = 0; j < 6; ++j) wv[j] = wl[k * 193 + tx + 32 * j];
                #pragma unroll
                for (int i = 0; i < 8; ++i) {
                    float xv = xs[(rb + ty * 8 + i) * 65 + k];
                    #pragma unroll
                    for (int j = 0; j < 6; ++j) acc[i][j] += xv * wv[j];
                }
            }
            const float* bb = in_b + l * 192;
            #pragma unroll
            for (int i = 0; i < 8; ++i)
                #pragma unroll
                for (int j = 0; j < 6; ++j) {
                    int n = tx + 32 * j;
                    qkv[(rb + ty * 8 + i) * 193 + n] = acc[i][j] + __ldg(bb + n);
                }
        }
        __syncthreads();

        // ---- attention (seq=2): one lane per (sample, head); ctx overwrites q slot ----
        {
            int sl = ((tid >> 5) << 3) + ((tid & 31) >> 2);   // sample_local 0..63
            int h  = tid & 3;                                  // head
            float* bp = qkv + (2 * sl) * 193 + h * 16;
            float s00 = 0.f, s01 = 0.f, s10 = 0.f, s11 = 0.f;
            #pragma unroll
            for (int d = 0; d < 16; ++d) {
                float q0 = bp[d],       q1 = bp[193 + d];
                float k0 = bp[64 + d],  k1 = bp[257 + d];
                s00 += q0 * k0; s01 += q0 * k1;
                s10 += q1 * k0; s11 += q1 * k1;
            }
            const float sc = 0.25f;   // 1/sqrt(16)
            s00 *= sc; s01 *= sc; s10 *= sc; s11 *= sc;
            float m0 = fmaxf(s00, s01), m1 = fmaxf(s10, s11);
            float e00 = expf(s00 - m0), e01 = expf(s01 - m0);
            float e10 = expf(s10 - m1), e11 = expf(s11 - m1);
            float i0 = 1.f / (e00 + e01), i1 = 1.f / (e10 + e11);
            float w00 = e00 * i0, w01 = e01 * i0;
            float w10 = e10 * i1, w11 = e11 * i1;
            #pragma unroll
            for (int d = 0; d < 16; ++d) {
                float v0 = bp[128 + d], v1 = bp[321 + d];
                bp[d]       = w00 * v0 + w01 * v1;
                bp[193 + d] = w10 * v0 + w11 * v1;
            }
        }
        // ---- out projection weights (reuse wl region; qkv/ctx untouched) ----
        stage_w(wl, out_w + l * 64 * 64, 64, 64, tid);
        __syncthreads();

        // ---- x += ctx @ out_w^T + out_b ----
        for (int rb = 0; rb < 128; rb += 64) {
            float acc[8][2];
            #pragma unroll
            for (int i = 0; i < 8; ++i) { acc[i][0] = 0.f; acc[i][1] = 0.f; }
            #pragma unroll 4
            for (int k = 0; k < 64; ++k) {
                float w0 = wl[k * 65 + tx];
                float w1 = wl[k * 65 + tx + 32];
                #pragma unroll
                for (int i = 0; i < 8; ++i) {
                    float xv = qkv[(rb + ty * 8 + i) * 193 + k];   // ctx in q slot
                    acc[i][0] += xv * w0;
                    acc[i][1] += xv * w1;
                }
            }
            #pragma unroll
            for (int i = 0; i < 8; ++i) {
                int row = rb + ty * 8 + i;
                #pragma unroll
                for (int j = 0; j < 2; ++j) {
                    int n = tx + 32 * j;
                    xs[row * 65 + n] += acc[i][j] + __ldg(out_b + l * 64 + n);
                }
            }
        }
        __syncthreads();
        if (tid < 128) ln_row(xs + tid * 65, ln1_g + l * 64, ln1_b + l * 64);
        __syncthreads();

        // ---- feed-forward: x += relu(x @ ff1^T + b1) @ ff2^T + b2 ----
        float* f1 = A;               // [64][257]
        float* f2 = A + 64 * 257;    // [256][65]
        float* hb = f2 + 256 * 65;   // [32][257]
        stage_w(f1, ff1_w + l * 256 * 64, 256, 64, tid);
        stage_w(f2, ff2_w + l * 64 * 256, 64, 256, tid);
        __syncthreads();

        for (int ch = 0; ch < 4; ++ch) {
            // pass 1: hidden = relu(x @ ff1^T + b1) for 32 rows
            float acc1[4][8];
            #pragma unroll
            for (int i = 0; i < 4; ++i)
                #pragma unroll
                for (int j = 0; j < 8; ++j) acc1[i][j] = 0.f;
            #pragma unroll 4
            for (int k = 0; k < 64; ++k) {
                float wv[8];
                #pragma unroll
                for (int j = 0; j < 8; ++j) wv[j] = f1[k * 257 + tx + 32 * j];
                #pragma unroll
                for (int i = 0; i < 4; ++i) {
                    float xv = xs[(ch * 32 + ty * 4 + i) * 65 + k];
                    #pragma unroll
                    for (int j = 0; j < 8; ++j) acc1[i][j] += xv * wv[j];
                }
            }
            #pragma unroll
            for (int i = 0; i < 4; ++i)
                #pragma unroll
                for (int j = 0; j < 8; ++j) {
                    int n = tx + 32 * j;
                    hb[(ty * 4 + i) * 257 + n] =
                        fmaxf(acc1[i][j] + __ldg(ff1_b + l * 256 + n), 0.f);
                }
            __syncthreads();

            // pass 2: x += hidden @ ff2^T + b2
            float acc2[4][2];
            #pragma unroll
            for (int i = 0; i < 4; ++i) { acc2[i][0] = 0.f; acc2[i][1] = 0.f; }
            #pragma unroll 4
            for (int k = 0; k < 256; ++k) {
                float w0 = f2[k * 65 + tx];
                float w1 = f2[k * 65 + tx + 32];
                #pragma unroll
                for (int i = 0; i < 4; ++i) {
                    float xv = hb[(ty * 4 + i) * 257 + k];
                    acc2[i][0] += xv * w0;
                    acc2[i][1] += xv * w1;
                }
            }
            #pragma unroll
            for (int i = 0; i < 4; ++i) {
                int row = ch * 32 + ty * 4 + i;
                #pragma unroll
                for (int j = 0; j < 2; ++j) {
                    int n = tx + 32 * j;
                    xs[row * 65 + n] += acc2[i][j] + __ldg(ff2_b + l * 64 + n);
                }
            }
            __syncthreads();
        }
        if (tid < 128) ln_row(xs + tid * 65, ln2_g + l * 64, ln2_b + l * 64);
        __syncthreads();
    }

    // ================= head: pred = relu(concat @ h1^T + b1) @ h2^T + b2 =================
    {
        float* h1  = A;              // [128][65]
        float* hb2 = A + 128 * 65;   // [64][65]
        stage_w(h1, h1_w, 64, 128, tid);
        __syncthreads();

        float acc[8][2];
        #pragma unroll
        for (int i = 0; i < 8; ++i) { acc[i][0] = 0.f; acc[i][1] = 0.f; }
        #pragma unroll 4
        for (int k = 0; k < 64; ++k) {           // first half of concat: pos 0 row
            float w0 = h1[k * 65 + tx];
            float w1 = h1[k * 65 + tx + 32];
            #pragma unroll
            for (int i = 0; i < 8; ++i) {
                float xv = xs[(2 * (ty * 8 + i)) * 65 + k];
                acc[i][0] += xv * w0;
                acc[i][1] += xv * w1;
            }
        }
        #pragma unroll 4
        for (int k = 64; k < 128; ++k) {         // second half: pos 1 row
            float w0 = h1[k * 65 + tx];
            float w1 = h1[k * 65 + tx + 32];
            #pragma unroll
            for (int i = 0; i < 8; ++i) {
                float xv = xs[(2 * (ty * 8 + i) + 1) * 65 + (k - 64)];
                acc[i][0] += xv * w0;
                acc[i][1] += xv * w1;
            }
        }
        #pragma unroll
        for (int i = 0; i < 8; ++i)
            #pragma unroll
            for (int j = 0; j < 2; ++j) {
                int n = tx + 32 * j;
                hb2[(ty * 8 + i) * 65 + n] = fmaxf(acc[i][j] + __ldg(h1_b + n), 0.f);
            }
        __syncthreads();

        if (tid < 64) {
            float p = __ldg(h2_b);
            #pragma unroll 8
            for (int n = 0; n < 64; ++n)
                p += hb2[tid * 65 + n] * __ldg(h2_w + n);
            out[s0 + tid] = p;
        }
    }
}

extern "C" void kernel_launch(void* const* d_in, const int* in_sizes, int n_in,
                              void* d_out, int out_size)
{
    const int*   user_idx      = (const int*)  d_in[0];
    const int*   item_idx      = (const int*)  d_in[1];
    const float* user_features = (const float*)d_in[2];
    const float* item_features = (const float*)d_in[3];
    const float* user_table    = (const float*)d_in[4];
    const float* item_table    = (const float*)d_in[5];
    const float* upw           = (const float*)d_in[6];
    const float* upb           = (const float*)d_in[7];
    const float* ipw           = (const float*)d_in[8];
    const float* ipb           = (const float*)d_in[9];
    const float* pe            = (const float*)d_in[10];
    const float* in_w          = (const float*)d_in[11];
    const float* in_b          = (const float*)d_in[12];
    const float* out_w         = (const float*)d_in[13];
    const float* out_b         = (const float*)d_in[14];
    const float* ln1_g         = (const float*)d_in[15];
    const float* ln1_b         = (const float*)d_in[16];
    const float* ff1_w         = (const float*)d_in[17];
    const float* ff1_b         = (const float*)d_in[18];
    const float* ff2_w         = (const float*)d_in[19];
    const float* ff2_b         = (const float*)d_in[20];
    const float* ln2_g         = (const float*)d_in[21];
    const float* ln2_b         = (const float*)d_in[22];
    const float* h1_w          = (const float*)d_in[23];
    const float* h1_b          = (const float*)d_in[24];
    const float* h2_w          = (const float*)d_in[25];
    const float* h2_b          = (const float*)d_in[26];
    float* out = (float*)d_out;

    const int B = in_sizes[0];           // user_idx element count = batch
    cudaFuncSetAttribute(TransformerRecSys_58806692217038_kernel,
                         cudaFuncAttributeMaxDynamicSharedMemorySize, SMEM_BYTES);

    TransformerRecSys_58806692217038_kernel<<<B / TILE, NTHR, SMEM_BYTES>>>(
        user_idx, item_idx, user_features, item_features, user_table, item_table,
        upw, upb, ipw, ipb, pe, in_w, in_b, out_w, out_b, ln1_g, ln1_b,
        ff1_w, ff1_b, ff2_w, ff2_b, ln2_g, ln2_b, h1_w, h1_b, h2_w, h2_b, out);
}

// round 4
// speedup vs baseline: 1.8338x; 1.7439x over previous
#include <cuda_runtime.h>
#include <cuda_bf16.h>
#include <cstdint>

#define NTHR 256

// ---------------- smem byte offsets ----------------
#define XS_OFF    0u          // fp32 [128][66]
#define S1_OFF    33792u      // fp32 [128][66] scratch (q, then v) / embed B (ipw)
#define S2_OFF    67584u      // fp32 [128][66] scratch (k)
#define XT_OFF    101376u     // bf16 [128][136] x tile   (embed A spans XT+CT)
#define CT_OFF    136192u     // bf16 [128][136] ctx/hidden tile
#define WB_OFF    171008u     // weights B region (52224 B)
#define WB2_OFF   (WB_OFF + 17408u)
#define SIDX_OFF  223232u     // int[128]
#define SMEM_TOTAL 223744u

#define ST64   136            // elems, K=64 tile stride (hi 0:64, lo 64:128)
#define ST128  264            // elems, K=128 tile stride
#define XSS    66             // floats, fp32 row stride

static __device__ __forceinline__ uint32_t smem_u32(const void* p) {
    uint32_t a;
    asm("{ .reg .u64 t; cvta.to.shared.u64 t, %1; cvt.u32.u64 %0, t; }" : "=r"(a) : "l"(p));
    return a;
}
static __device__ __forceinline__ void ldmA(uint32_t a[4], uint32_t addr) {
    asm volatile("ldmatrix.sync.aligned.m8n8.x4.shared.b16 {%0,%1,%2,%3}, [%4];"
                 : "=r"(a[0]), "=r"(a[1]), "=r"(a[2]), "=r"(a[3]) : "r"(addr));
}
static __device__ __forceinline__ void ldmB(uint32_t b[2], uint32_t addr) {
    asm volatile("ldmatrix.sync.aligned.m8n8.x2.shared.b16 {%0,%1}, [%2];"
                 : "=r"(b[0]), "=r"(b[1]) : "r"(addr));
}
static __device__ __forceinline__ void mma16816(float d[4], const uint32_t a[4], const uint32_t b[2]) {
    asm volatile("mma.sync.aligned.m16n8k16.row.col.f32.bf16.bf16.f32 "
                 "{%0,%1,%2,%3}, {%4,%5,%6,%7}, {%8,%9}, {%0,%1,%2,%3};"
                 : "+f"(d[0]), "+f"(d[1]), "+f"(d[2]), "+f"(d[3])
                 : "r"(a[0]), "r"(a[1]), "r"(a[2]), "r"(a[3]), "r"(b[0]), "r"(b[1]));
}

// D[16 rows x 64] += 3-term compensated A[16 x K] * B[64 x K]^T
// A tile rows at aBase (warp row-block base), hi cols 0:K, lo K:2K. B same.
template<int NKC>   // NKC = K/16
static __device__ __forceinline__ void gemm3(float (*acc)[4], uint32_t aBase, int aStrB,
                                             uint32_t bBase, int bStrB) {
    const int lane = threadIdx.x & 31;
    const int KB = NKC * 32;            // byte offset of lo block
    uint32_t aAddr = aBase + (lane & 15) * aStrB + ((lane >> 4) << 4);
    uint32_t bAddr = bBase + (lane & 7) * bStrB + (((lane >> 3) & 1) << 4);
    #pragma unroll
    for (int kc = 0; kc < NKC; ++kc) {
        uint32_t ah[4], al[4];
        ldmA(ah, aAddr + kc * 32);
        ldmA(al, aAddr + kc * 32 + KB);
        #pragma unroll
        for (int j = 0; j < 8; ++j) {
            uint32_t bh[2], bl[2];
            uint32_t ba = bAddr + j * 8 * bStrB + kc * 32;
            ldmB(bh, ba);
            mma16816(acc[j], ah, bh);
            mma16816(acc[j], al, bh);
            ldmB(bl, ba + KB);
            mma16816(acc[j], ah, bl);
        }
    }
}

// stage gmem fp32 [N][rs] (use cols 0:K) -> smem bf16 hi/lo tile [N][strideElems]
static __device__ void stage_w(char* sm, uint32_t off, const float* __restrict__ w,
                               int rs, int N, int K, int khalf_log, int strideElems, int tid) {
    int total = N * (K >> 1);
    for (int idx = tid; idx < total; idx += NTHR) {
        int n  = idx >> khalf_log;
        int k2 = (idx - (n << khalf_log)) << 1;
        float2 f = *reinterpret_cast<const float2*>(w + (size_t)n * rs + k2);
        __nv_bfloat16 h0 = __float2bfloat16(f.x), h1 = __float2bfloat16(f.y);
        __nv_bfloat162 hh; hh.x = h0; hh.y = h1;
        __nv_bfloat162 ll;
        ll.x = __float2bfloat16(f.x - __bfloat162float(h0));
        ll.y = __float2bfloat16(f.y - __bfloat162float(h1));
        __nv_bfloat16* row = (__nv_bfloat16*)(sm + off) + (size_t)n * strideElems;
        *reinterpret_cast<__nv_bfloat162*>(row + k2)     = hh;
        *reinterpret_cast<__nv_bfloat162*>(row + K + k2) = ll;
    }
}

static __device__ __forceinline__ void st_hilo(char* sm, uint32_t off, int strideElems,
                                               int r, int c, int K, float f0, float f1) {
    __nv_bfloat16 h0 = __float2bfloat16(f0), h1 = __float2bfloat16(f1);
    __nv_bfloat162 hh; hh.x = h0; hh.y = h1;
    __nv_bfloat162 ll;
    ll.x = __float2bfloat16(f0 - __bfloat162float(h0));
    ll.y = __float2bfloat16(f1 - __bfloat162float(h1));
    __nv_bfloat16* row = (__nv_bfloat16*)(sm + off) + (size_t)r * strideElems;
    *reinterpret_cast<__nv_bfloat162*>(row + c)     = hh;
    *reinterpret_cast<__nv_bfloat162*>(row + K + c) = ll;
}

// convert one xs row half (32 cols) -> XT tile (no LN)
static __device__ __forceinline__ void conv_half(char* sm, const float* xsrow, int r, int cbase) {
    #pragma unroll
    for (int c = cbase; c < cbase + 32; c += 2)
        st_hilo(sm, XT_OFF, ST64, r, c, 64, xsrow[c], xsrow[c + 1]);
}

// LayerNorm one full xs row in place + write XT hi/lo
static __device__ void ln_conv(char* sm, float* xsrow, const float* g, const float* b, int r) {
    float m = 0.f;
    #pragma unroll
    for (int c = 0; c < 64; ++c) m += xsrow[c];
    m *= (1.f / 64.f);
    float v = 0.f;
    #pragma unroll
    for (int c = 0; c < 64; ++c) { float d = xsrow[c] - m; v += d * d; }
    v *= (1.f / 64.f);
    float inv = rsqrtf(v + 1e-5f);
    #pragma unroll
    for (int c = 0; c < 64; c += 2) {
        float f0 = (xsrow[c]     - m) * inv * __ldg(g + c)     + __ldg(b + c);
        float f1 = (xsrow[c + 1] - m) * inv * __ldg(g + c + 1) + __ldg(b + c + 1);
        xsrow[c] = f0; xsrow[c + 1] = f1;
        st_hilo(sm, XT_OFF, ST64, r, c, 64, f0, f1);
    }
}

__global__ void __launch_bounds__(NTHR, 1)
TransformerRecSys_58806692217038_kernel(
    const int*   __restrict__ user_idx,   const int*   __restrict__ item_idx,
    const float* __restrict__ user_features, const float* __restrict__ item_features,
    const float* __restrict__ user_table, const float* __restrict__ item_table,
    const float* __restrict__ upw, const float* __restrict__ upb,
    const float* __restrict__ ipw, const float* __restrict__ ipb,
    const float* __restrict__ pe,
    const float* __restrict__ in_w, const float* __restrict__ in_b,
    const float* __restrict__ out_w, const float* __restrict__ out_b,
    const float* __restrict__ ln1_g, const float* __restrict__ ln1_b,
    const float* __restrict__ ff1_w, const float* __restrict__ ff1_b,
    const float* __restrict__ ff2_w, const float* __restrict__ ff2_b,
    const float* __restrict__ ln2_g, const float* __restrict__ ln2_b,
    const float* __restrict__ h1_w, const float* __restrict__ h1_b,
    const float* __restrict__ h2_w, const float* __restrict__ h2_b,
    float* __restrict__ out)
{
    extern __shared__ char sm[];
    const int tid  = threadIdx.x;
    const int lane = tid & 31;
    const int w    = tid >> 5;
    const int s0   = blockIdx.x << 6;

    float* xs   = (float*)(sm + XS_OFF);
    int*   sidx = (int*)(sm + SIDX_OFF);

    const uint32_t xt_u = smem_u32(sm + XT_OFF);
    const uint32_t ct_u = smem_u32(sm + CT_OFF);
    const uint32_t wb_u = smem_u32(sm + WB_OFF);
    const uint32_t s1_u = smem_u32(sm + S1_OFF);

    if (tid < 64)        sidx[tid] = user_idx[s0 + tid];
    else if (tid < 128)  sidx[tid] = item_idx[s0 + tid - 64];

    // ---- embed staging: A rows 0-63 user feats, 64-127 item feats (K=128, stride 264) ----
    stage_w(sm, XT_OFF,                  user_features + (size_t)s0 * 128, 128, 64, 128, 6, ST128, tid);
    stage_w(sm, XT_OFF + 64u * ST128 * 2, item_features + (size_t)s0 * 128, 128, 64, 128, 6, ST128, tid);
    stage_w(sm, WB_OFF, upw, 128, 64, 128, 6, ST128, tid);
    stage_w(sm, S1_OFF, ipw, 128, 64, 128, 6, ST128, tid);
    __syncthreads();

    // ---- embed GEMM: warps 0-3 users (B=upw), 4-7 items (B=ipw) ----
    {
        float acc[8][4];
        #pragma unroll
        for (int j = 0; j < 8; ++j) { acc[j][0] = acc[j][1] = acc[j][2] = acc[j][3] = 0.f; }
        gemm3<8>(acc, xt_u + (uint32_t)(16 * w) * (ST128 * 2), ST128 * 2,
                 (w < 4 ? wb_u : s1_u), ST128 * 2);

        const int side = w >> 2;
        const float* bb  = side ? ipb : upb;
        const float* tbl = side ? item_table : user_table;
        const float* pep = pe + side * 64;
        const int r0 = 16 * w + (lane >> 2);      // A_emb row
        const int sA = (side ? r0 - 64 : r0);     // sample of r0
        const int sB = sA + 8;                    // sample of r0+8
        size_t tA = (size_t)sidx[side * 64 + sA] * 64;
        size_t tB = (size_t)sidx[side * 64 + sB] * 64;
        float* xrA = xs + (2 * sA + side) * XSS;
        float* xrB = xs + (2 * sB + side) * XSS;
        #pragma unroll
        for (int j = 0; j < 8; ++j) {
            int c = 8 * j + 2 * (lane & 3);
            xrA[c]     = acc[j][0] + __ldg(bb + c)     + __ldg(tbl + tA + c)     + __ldg(pep + c);
            xrA[c + 1] = acc[j][1] + __ldg(bb + c + 1) + __ldg(tbl + tA + c + 1) + __ldg(pep + c + 1);
            xrB[c]     = acc[j][2] + __ldg(bb + c)     + __ldg(tbl + tB + c)     + __ldg(pep + c);
            xrB[c + 1] = acc[j][3] + __ldg(bb + c + 1) + __ldg(tbl + tB + c + 1) + __ldg(pep + c + 1);
        }
    }
    __syncthreads();

    // ---- convert xs -> XT [128][136] (2 lanes per row) ----
    {
        int r = 16 * w + (lane >> 1);
        conv_half(sm, xs + r * XSS, r, (lane & 1) * 32);
        __syncwarp();
    }

    const uint32_t aW = xt_u + (uint32_t)w * (16 * ST64 * 2);   // warp's x-tile row block
    const uint32_t cW = ct_u + (uint32_t)w * (16 * ST64 * 2);

    // ================= transformer layers =================
    for (int l = 0; l < 2; ++l) {
        __syncthreads();                      // WB free, XT ready
        stage_w(sm, WB_OFF, in_w + (size_t)l * 192 * 64, 64, 192, 64, 5, ST64, tid);
        __syncthreads();

        // ---- q,k,v chunks + attention ----
        float w00, w01, w10, w11;             // softmax weights (per lane unit)
        const int si = lane >> 2, hh = lane & 3;
        const int ra = 16 * w + 2 * si, rb = ra + 1;
        float* S1 = (float*)(sm + S1_OFF);
        float* S2 = (float*)(sm + S2_OFF);

        for (int ch = 0; ch < 3; ++ch) {
            float acc[8][4];
            #pragma unroll
            for (int j = 0; j < 8; ++j) { acc[j][0] = acc[j][1] = acc[j][2] = acc[j][3] = 0.f; }
            gemm3<4>(acc, aW, ST64 * 2, wb_u + (uint32_t)ch * (64 * ST64 * 2), ST64 * 2);

            float* scr = (ch == 1) ? S2 : S1;
            const float* bb = in_b + l * 192 + ch * 64;
            int r0 = 16 * w + (lane >> 2);
            #pragma unroll
            for (int j = 0; j < 8; ++j) {
                int c = 8 * j + 2 * (lane & 3);
                scr[r0 * XSS + c]           = acc[j][0] + __ldg(bb + c);
                scr[r0 * XSS + c + 1]       = acc[j][1] + __ldg(bb + c + 1);
                scr[(r0 + 8) * XSS + c]     = acc[j][2] + __ldg(bb + c);
                scr[(r0 + 8) * XSS + c + 1] = acc[j][3] + __ldg(bb + c + 1);
            }
            __syncwarp();

            if (ch == 1) {                    // scores from q (S1), k (S2)
                const float* qa = S1 + ra * XSS + hh * 16;
                const float* qb = S1 + rb * XSS + hh * 16;
                const float* ka = S2 + ra * XSS + hh * 16;
                const float* kb = S2 + rb * XSS + hh * 16;
                float s00 = 0.f, s01 = 0.f, s10 = 0.f, s11 = 0.f;
                #pragma unroll
                for (int d = 0; d < 16; ++d) {
                    float q0 = qa[d], q1 = qb[d], k0 = ka[d], k1 = kb[d];
                    s00 += q0 * k0; s01 += q0 * k1;
                    s10 += q1 * k0; s11 += q1 * k1;
                }
                s00 *= 0.25f; s01 *= 0.25f; s10 *= 0.25f; s11 *= 0.25f;
                float m0 = fmaxf(s00, s01), m1 = fmaxf(s10, s11);
                float e00 = expf(s00 - m0), e01 = expf(s01 - m0);
                float e10 = expf(s10 - m1), e11 = expf(s11 - m1);
                float i0 = 1.f / (e00 + e01), i1 = 1.f / (e10 + e11);
                w00 = e00 * i0; w01 = e01 * i0;
                w10 = e10 * i1; w11 = e11 * i1;
                __syncwarp();                 // q reads done before v overwrites S1
            }
        }
        // ---- ctx from v (S1) -> CT tile ----
        {
            const float* va = S1 + ra * XSS + hh * 16;
            const float* vb = S1 + rb * XSS + hh * 16;
            #pragma unroll
            for (int d = 0; d < 16; d += 2) {
                float v00 = va[d], v01 = va[d + 1], v10 = vb[d], v11 = vb[d + 1];
                int c = hh * 16 + d;
                st_hilo(sm, CT_OFF, ST64, ra, c, 64, w00 * v00 + w01 * v10, w00 * v01 + w01 * v11);
                st_hilo(sm, CT_OFF, ST64, rb, c, 64, w10 * v00 + w11 * v10, w10 * v01 + w11 * v11);
            }
            __syncwarp();
        }
        __syncthreads();
        stage_w(sm, WB_OFF, out_w + (size_t)l * 4096, 64, 64, 64, 5, ST64, tid);
        __syncthreads();

        // ---- out-proj + residual + LN1 ----
        {
            float acc[8][4];
            #pragma unroll
            for (int j = 0; j < 8; ++j) { acc[j][0] = acc[j][1] = acc[j][2] = acc[j][3] = 0.f; }
            gemm3<4>(acc, cW, ST64 * 2, wb_u, ST64 * 2);
            const float* bb = out_b + l * 64;
            int r0 = 16 * w + (lane >> 2);
            #pragma unroll
            for (int j = 0; j < 8; ++j) {
                int c = 8 * j + 2 * (lane & 3);
                xs[r0 * XSS + c]           += acc[j][0] + __ldg(bb + c);
                xs[r0 * XSS + c + 1]       += acc[j][1] + __ldg(bb + c + 1);
                xs[(r0 + 8) * XSS + c]     += acc[j][2] + __ldg(bb + c);
                xs[(r0 + 8) * XSS + c + 1] += acc[j][3] + __ldg(bb + c + 1);
            }
            __syncwarp();
            if (lane < 16) ln_conv(sm, xs + (16 * w + lane) * XSS, ln1_g + l * 64, ln1_b + l * 64, 16 * w + lane);
            __syncwarp();
        }

        // ---- FF fused over 4 chunks of 64 hidden units ----
        {
            float accF[8][4];
            #pragma unroll
            for (int j = 0; j < 8; ++j) { accF[j][0] = accF[j][1] = accF[j][2] = accF[j][3] = 0.f; }
            for (int c4 = 0; c4 < 4; ++c4) {
                __syncthreads();
                stage_w(sm, WB_OFF,  ff1_w + ((size_t)l * 256 + 64 * c4) * 64, 64,  64, 64, 5, ST64, tid);
                stage_w(sm, WB2_OFF, ff2_w + (size_t)l * 64 * 256 + 64 * c4,   256, 64, 64, 5, ST64, tid);
                __syncthreads();

                float acc[8][4];
                #pragma unroll
                for (int j = 0; j < 8; ++j) { acc[j][0] = acc[j][1] = acc[j][2] = acc[j][3] = 0.f; }
                gemm3<4>(acc, aW, ST64 * 2, wb_u, ST64 * 2);

                const float* b1 = ff1_b + l * 256 + 64 * c4;
                int r0 = 16 * w + (lane >> 2);
                #pragma unroll
                for (int j = 0; j < 8; ++j) {
                    int c = 8 * j + 2 * (lane & 3);
                    st_hilo(sm, CT_OFF, ST64, r0, c, 64,
                            fmaxf(acc[j][0] + __ldg(b1 + c), 0.f),
                            fmaxf(acc[j][1] + __ldg(b1 + c + 1), 0.f));
                    st_hilo(sm, CT_OFF, ST64, r0 + 8, c, 64,
                            fmaxf(acc[j][2] + __ldg(b1 + c), 0.f),
                            fmaxf(acc[j][3] + __ldg(b1 + c + 1), 0.f));
                }
                __syncwarp();
                gemm3<4>(accF, cW, ST64 * 2, smem_u32(sm + WB2_OFF), ST64 * 2);
            }
            const float* b2 = ff2_b + l * 64;
            int r0 = 16 * w + (lane >> 2);
            #pragma unroll
            for (int j = 0; j < 8; ++j) {
                int c = 8 * j + 2 * (lane & 3);
                xs[r0 * XSS + c]           += accF[j][0] + __ldg(b2 + c);
                xs[r0 * XSS + c + 1]       += accF[j][1] + __ldg(b2 + c + 1);
                xs[(r0 + 8) * XSS + c]     += accF[j][2] + __ldg(b2 + c);
                xs[(r0 + 8) * XSS + c + 1] += accF[j][3] + __ldg(b2 + c + 1);
            }
            __syncwarp();
            if (lane < 16) ln_conv(sm, xs + (16 * w + lane) * XSS, ln2_g + l * 64, ln2_b + l * 64, 16 * w + lane);
            __syncwarp();
        }
    }

    // ================= head =================
    __syncthreads();
    // build A_head [64][264]: row s = concat(xs[2s], xs[2s+1]); overwrite XT region
    for (int idx = tid; idx < 64 * 64; idx += NTHR) {
        int s = idx >> 6, k2 = (idx & 63) << 1;
        int hf = k2 >> 6, c = k2 & 63;
        const float* xr = xs + (2 * s + hf) * XSS;
        st_hilo(sm, XT_OFF, ST128, s, k2, 128, xr[c], xr[c + 1]);
    }
    stage_w(sm, WB_OFF, h1_w, 128, 64, 128, 6, ST128, tid);
    __syncthreads();

    if (w < 4) {
        float acc[8][4];
        #pragma unroll
        for (int j = 0; j < 8; ++j) { acc[j][0] = acc[j][1] = acc[j][2] = acc[j][3] = 0.f; }
        gemm3<8>(acc, xt_u + (uint32_t)(16 * w) * (ST128 * 2), ST128 * 2, wb_u, ST128 * 2);

        float p0 = 0.f, p1 = 0.f;
        #pragma unroll
        for (int j = 0; j < 8; ++j) {
            int c = 8 * j + 2 * (lane & 3);
            float b0 = __ldg(h1_b + c), b1 = __ldg(h1_b + c + 1);
            float w0 = __ldg(h2_w + c), w1 = __ldg(h2_w + c + 1);
            p0 += fmaxf(acc[j][0] + b0, 0.f) * w0 + fmaxf(acc[j][1] + b1, 0.f) * w1;
            p1 += fmaxf(acc[j][2] + b0, 0.f) * w0 + fmaxf(acc[j][3] + b1, 0.f) * w1;
        }
        p0 += __shfl_xor_sync(0xffffffffu, p0, 1);
        p0 += __shfl_xor_sync(0xffffffffu, p0, 2);
        p1 += __shfl_xor_sync(0xffffffffu, p1, 1);
        p1 += __shfl_xor_sync(0xffffffffu, p1, 2);
        if ((lane & 3) == 0) {
            float hb = __ldg(h2_b);
            int s = 16 * w + (lane >> 2);
            out[s0 + s]     = p0 + hb;
            out[s0 + s + 8] = p1 + hb;
        }
    }
}

extern "C" void kernel_launch(void* const* d_in, const int* in_sizes, int n_in,
                              void* d_out, int out_size)
{
    const int*   user_idx      = (const int*)  d_in[0];
    const int*   item_idx      = (const int*)  d_in[1];
    const float* user_features = (const float*)d_in[2];
    const float* item_features = (const float*)d_in[3];
    const float* user_table    = (const float*)d_in[4];
    const float* item_table    = (const float*)d_in[5];
    const float* upw           = (const float*)d_in[6];
    const float* upb           = (const float*)d_in[7];
    const float* ipw           = (const float*)d_in[8];
    const float* ipb           = (const float*)d_in[9];
    const float* pe            = (const float*)d_in[10];
    const float* in_w          = (const float*)d_in[11];
    const float* in_b          = (const float*)d_in[12];
    const float* out_w         = (const float*)d_in[13];
    const float* out_b         = (const float*)d_in[14];
    const float* ln1_g         = (const float*)d_in[15];
    const float* ln1_b         = (const float*)d_in[16];
    const float* ff1_w         = (const float*)d_in[17];
    const float* ff1_b         = (const float*)d_in[18];
    const float* ff2_w         = (const float*)d_in[19];
    const float* ff2_b         = (const float*)d_in[20];
    const float* ln2_g         = (const float*)d_in[21];
    const float* ln2_b         = (const float*)d_in[22];
    const float* h1_w          = (const float*)d_in[23];
    const float* h1_b          = (const float*)d_in[24];
    const float* h2_w          = (const float*)d_in[25];
    const float* h2_b          = (const float*)d_in[26];
    float* out = (float*)d_out;

    const int B = in_sizes[0];
    cudaFuncSetAttribute(TransformerRecSys_58806692217038_kernel,
                         cudaFuncAttributeMaxDynamicSharedMemorySize, SMEM_TOTAL);

    TransformerRecSys_58806692217038_kernel<<<B / 64, NTHR, SMEM_TOTAL>>>(
        user_idx, item_idx, user_features, item_features, user_table, item_table,
        upw, upb, ipw, ipb, pe, in_w, in_b, out_w, out_b, ln1_g, ln1_b,
        ff1_w, ff1_b, ff2_w, ff2_b, ln2_g, ln2_b, h1_w, h1_b, h2_w, h2_b, out);
}

// round 5
// speedup vs baseline: 2.6610x; 1.4511x over previous
#include <cuda_runtime.h>
#include <cuda_bf16.h>
#include <cstdint>

#define MAXB 131072

// ---------------- persistent device scratch (no runtime allocation) ----------------
__device__ __align__(16) float          g_x0[(size_t)MAXB * 2 * 64];       // [token][64]
__device__ __align__(16) unsigned char  g_wbuf[24 * 17408 + 33792];        // weight tile images

// ---------------- common helpers ----------------
static __device__ __forceinline__ uint32_t smem_u32(const void* p) {
    uint32_t a;
    asm("{ .reg .u64 t; cvta.to.shared.u64 t, %1; cvt.u32.u64 %0, t; }" : "=r"(a) : "l"(p));
    return a;
}
static __device__ __forceinline__ void ldmA(uint32_t a[4], uint32_t addr) {
    asm volatile("ldmatrix.sync.aligned.m8n8.x4.shared.b16 {%0,%1,%2,%3}, [%4];"
                 : "=r"(a[0]), "=r"(a[1]), "=r"(a[2]), "=r"(a[3]) : "r"(addr));
}
static __device__ __forceinline__ void ldmB(uint32_t b[2], uint32_t addr) {
    asm volatile("ldmatrix.sync.aligned.m8n8.x2.shared.b16 {%0,%1}, [%2];"
                 : "=r"(b[0]), "=r"(b[1]) : "r"(addr));
}
static __device__ __forceinline__ void mma16816(float d[4], const uint32_t a[4], const uint32_t b[2]) {
    asm volatile("mma.sync.aligned.m16n8k16.row.col.f32.bf16.bf16.f32 "
                 "{%0,%1,%2,%3}, {%4,%5,%6,%7}, {%8,%9}, {%0,%1,%2,%3};"
                 : "+f"(d[0]), "+f"(d[1]), "+f"(d[2]), "+f"(d[3])
                 : "r"(a[0]), "r"(a[1]), "r"(a[2]), "r"(a[3]), "r"(b[0]), "r"(b[1]));
}

// 3-term compensated D[16x64] += A[16xK] * B[64xK]^T  (strides in BYTES)
template<int NKC>
static __device__ __forceinline__ void gemm3(float (*acc)[4], uint32_t aBase, int aStrB,
                                             uint32_t bBase, int bStrB) {
    const int lane = threadIdx.x & 31;
    const int KB = NKC * 32;
    uint32_t aAddr = aBase + (lane & 15) * aStrB + ((lane >> 4) << 4);
    uint32_t bAddr = bBase + (lane & 7) * bStrB + (((lane >> 3) & 1) << 4);
    #pragma unroll
    for (int kc = 0; kc < NKC; ++kc) {
        uint32_t ah[4], al[4];
        ldmA(ah, aAddr + kc * 32);
        ldmA(al, aAddr + kc * 32 + KB);
        #pragma unroll
        for (int j = 0; j < 8; ++j) {
            uint32_t bh[2], bl[2];
            uint32_t ba = bAddr + j * 8 * bStrB + kc * 32;
            ldmB(bh, ba);
            mma16816(acc[j], ah, bh);
            mma16816(acc[j], al, bh);
            ldmB(bl, ba + KB);
            mma16816(acc[j], ah, bl);
        }
    }
}

// hi/lo bf16 pair store into padded tile [r][strideElems], hi cols 0:K, lo K:2K
static __device__ __forceinline__ void st_hilo(char* sm, uint32_t off, int strideElems,
                                               int r, int c, int K, float f0, float f1) {
    __nv_bfloat16 h0 = __float2bfloat16(f0), h1 = __float2bfloat16(f1);
    __nv_bfloat162 hh; hh.x = h0; hh.y = h1;
    __nv_bfloat162 ll;
    ll.x = __float2bfloat16(f0 - __bfloat162float(h0));
    ll.y = __float2bfloat16(f1 - __bfloat162float(h1));
    __nv_bfloat16* row = (__nv_bfloat16*)(sm + off) + (size_t)r * strideElems;
    *reinterpret_cast<__nv_bfloat162*>(row + c)     = hh;
    *reinterpret_cast<__nv_bfloat162*>(row + K + c) = ll;
}

// =====================================================================================
// Pre-kernel A: convert all weights to hi/lo tile images
//   chunks 0..23: [64][64] K-chunks, image [64 rows][272B]  (hi 128B | lo 128B | pad 16B)
//   chunk 24:     h1_w [64][128],   image [64 rows][528B]  (hi 256B | lo 256B | pad 16B)
// =====================================================================================
__global__ void conv_w_kernel(const float* __restrict__ in_w, const float* __restrict__ out_w,
                              const float* __restrict__ ff1_w, const float* __restrict__ ff2_w,
                              const float* __restrict__ h1_w)
{
    int b = blockIdx.x;
    if (b < 24) {
        int l = b / 12, c = b % 12;
        const float* src; int rs;
        if (c < 3)       { src = in_w  + ((size_t)l * 192 + 64 * c) * 64; rs = 64; }
        else if (c == 3) { src = out_w + (size_t)l * 4096;                rs = 64; }
        else {
            int cc = (c - 4) >> 1;
            if (((c - 4) & 1) == 0) { src = ff1_w + ((size_t)l * 256 + 64 * cc) * 64; rs = 64;  }
            else                    { src = ff2_w + (size_t)l * 16384 + 64 * cc;      rs = 256; }
        }
        unsigned char* dst = g_wbuf + (size_t)b * 17408;
        for (int idx = threadIdx.x; idx < 64 * 32; idx += 256) {
            int n = idx >> 5, k2 = (idx & 31) << 1;
            float2 f = *reinterpret_cast<const float2*>(src + (size_t)n * rs + k2);
            __nv_bfloat16 h0 = __float2bfloat16(f.x), h1 = __float2bfloat16(f.y);
            __nv_bfloat162 hh; hh.x = h0; hh.y = h1;
            __nv_bfloat162 ll;
            ll.x = __float2bfloat16(f.x - __bfloat162float(h0));
            ll.y = __float2bfloat16(f.y - __bfloat162float(h1));
            *reinterpret_cast<__nv_bfloat162*>(dst + n * 272 + k2 * 2)       = hh;
            *reinterpret_cast<__nv_bfloat162*>(dst + n * 272 + 128 + k2 * 2) = ll;
        }
    } else {
        unsigned char* dst = g_wbuf + 24 * 17408;
        for (int idx = threadIdx.x; idx < 64 * 64; idx += 256) {
            int n = idx >> 6, k2 = (idx & 63) << 1;
            float2 f = *reinterpret_cast<const float2*>(h1_w + (size_t)n * 128 + k2);
            __nv_bfloat16 h0 = __float2bfloat16(f.x), h1 = __float2bfloat16(f.y);
            __nv_bfloat162 hh; hh.x = h0; hh.y = h1;
            __nv_bfloat162 ll;
            ll.x = __float2bfloat16(f.x - __bfloat162float(h0));
            ll.y = __float2bfloat16(f.y - __bfloat162float(h1));
            *reinterpret_cast<__nv_bfloat162*>(dst + n * 528 + k2 * 2)       = hh;
            *reinterpret_cast<__nv_bfloat162*>(dst + n * 528 + 256 + k2 * 2) = ll;
        }
    }
}

// =====================================================================================
// Pre-kernel B: embedding projection -> g_x0[token][64] = feat@W^T + b + table[idx] + pe
// grid B/64, 256 threads. smem: featA [128][528B] | upw [64][528B] | ipw [64][528B] | sidx
// =====================================================================================
#define EB_FEAT 0u
#define EB_WU   67584u
#define EB_WI   101376u
#define EB_SIDX 135168u
#define EB_SMEM 135680u

static __device__ void stage_hilo128(char* sm, uint32_t off, const float* __restrict__ w,
                                     int nRows, int tid) {
    for (int idx = tid; idx < nRows * 64; idx += 256) {
        int n = idx >> 6, k2 = (idx & 63) << 1;
        float2 f = *reinterpret_cast<const float2*>(w + (size_t)n * 128 + k2);
        __nv_bfloat16 h0 = __float2bfloat16(f.x), h1 = __float2bfloat16(f.y);
        __nv_bfloat162 hh; hh.x = h0; hh.y = h1;
        __nv_bfloat162 ll;
        ll.x = __float2bfloat16(f.x - __bfloat162float(h0));
        ll.y = __float2bfloat16(f.y - __bfloat162float(h1));
        char* row = sm + off + (size_t)n * 528;
        *reinterpret_cast<__nv_bfloat162*>(row + k2 * 2)       = hh;
        *reinterpret_cast<__nv_bfloat162*>(row + 256 + k2 * 2) = ll;
    }
}

__global__ void __launch_bounds__(256, 1)
embed_kernel(const int* __restrict__ user_idx, const int* __restrict__ item_idx,
             const float* __restrict__ user_features, const float* __restrict__ item_features,
             const float* __restrict__ user_table, const float* __restrict__ item_table,
             const float* __restrict__ upw, const float* __restrict__ upb,
             const float* __restrict__ ipw, const float* __restrict__ ipb,
             const float* __restrict__ pe)
{
    extern __shared__ char sm[];
    const int tid = threadIdx.x, lane = tid & 31, w = tid >> 5;
    const int s0 = blockIdx.x << 6;
    int* sidx = (int*)(sm + EB_SIDX);

    if (tid < 64)       sidx[tid] = user_idx[s0 + tid];
    else if (tid < 128) sidx[tid] = item_idx[s0 + tid - 64];

    stage_hilo128(sm, EB_FEAT,               user_features + (size_t)s0 * 128, 64, tid);
    stage_hilo128(sm, EB_FEAT + 64u * 528u,  item_features + (size_t)s0 * 128, 64, tid);
    stage_hilo128(sm, EB_WU, upw, 64, tid);
    stage_hilo128(sm, EB_WI, ipw, 64, tid);
    __syncthreads();

    float acc[8][4];
    #pragma unroll
    for (int j = 0; j < 8; ++j) { acc[j][0] = acc[j][1] = acc[j][2] = acc[j][3] = 0.f; }
    gemm3<8>(acc, smem_u32(sm + EB_FEAT) + (uint32_t)(16 * w) * 528u, 528,
             smem_u32(sm + (w < 4 ? EB_WU : EB_WI)), 528);

    const int side = w >> 2;
    const int qr = lane >> 2, qc = lane & 3;
    const int r0 = 16 * w + qr;
    const int sA = side ? r0 - 64 : r0;
    const int sB = sA + 8;
    const float* bb  = side ? ipb : upb;
    const float* tbl = side ? item_table : user_table;
    const float* pep = pe + side * 64;
    size_t tA = (size_t)sidx[side * 64 + sA] * 64;
    size_t tB = (size_t)sidx[side * 64 + sB] * 64;
    float* dA = g_x0 + ((size_t)(s0 + sA) * 2 + side) * 64;
    float* dB = g_x0 + ((size_t)(s0 + sB) * 2 + side) * 64;
    #pragma unroll
    for (int j = 0; j < 8; ++j) {
        int c = 8 * j + 2 * qc;
        dA[c]     = acc[j][0] + __ldg(bb + c)     + __ldg(tbl + tA + c)     + __ldg(pep + c);
        dA[c + 1] = acc[j][1] + __ldg(bb + c + 1) + __ldg(tbl + tA + c + 1) + __ldg(pep + c + 1);
        dB[c]     = acc[j][2] + __ldg(bb + c)     + __ldg(tbl + tB + c)     + __ldg(pep + c);
        dB[c + 1] = acc[j][3] + __ldg(bb + c + 1) + __ldg(tbl + tB + c + 1) + __ldg(pep + c + 1);
    }
}

// =====================================================================================
// Main kernel: 128 threads, 32 samples (64 token rows), 3 CTAs/SM
// smem: XT [64][272B] @0 | CT [64][272B] @17408 | WB 2x17408 @34816   total 69632
// =====================================================================================
#define XT_OFF 0u
#define CT_OFF 17408u
#define WB_OFF 34816u
#define MAIN_SMEM 69632u

#define CP16(dst, src) asm volatile("cp.async.cg.shared.global [%0], [%1], 16;" \
                                    :: "r"(dst), "l"(src) : "memory")
#define CP_COMMIT() asm volatile("cp.async.commit_group;" ::: "memory")
#define CP_WAIT0()  asm volatile("cp.async.wait_group 0;" ::: "memory")

static __device__ __forceinline__ void stage_cp(uint32_t dst, const unsigned char* src,
                                                int bytes, int tid) {
    for (int o = tid * 16; o < bytes; o += 128 * 16)
        CP16(dst + o, src + o);
}

// LN over one register row (16 vals/lane spread over 4 qc lanes), write hi/lo tile
static __device__ __forceinline__ void ln_reg(float v[8][2], const float* g, const float* b,
                                              char* sm, uint32_t off, int strideE,
                                              int row, int colbase, int K, int qc)
{
    float s = 0.f;
    #pragma unroll
    for (int j = 0; j < 8; ++j) s += v[j][0] + v[j][1];
    s += __shfl_xor_sync(0xffffffffu, s, 1);
    s += __shfl_xor_sync(0xffffffffu, s, 2);
    float m = s * (1.f / 64.f);
    float var = 0.f;
    #pragma unroll
    for (int j = 0; j < 8; ++j) {
        float d0 = v[j][0] - m, d1 = v[j][1] - m;
        var += d0 * d0 + d1 * d1;
    }
    var += __shfl_xor_sync(0xffffffffu, var, 1);
    var += __shfl_xor_sync(0xffffffffu, var, 2);
    float inv = rsqrtf(var * (1.f / 64.f) + 1e-5f);
    #pragma unroll
    for (int j = 0; j < 8; ++j) {
        int cc = 8 * j + 2 * qc;
        float f0 = (v[j][0] - m) * inv * __ldg(g + cc)     + __ldg(b + cc);
        float f1 = (v[j][1] - m) * inv * __ldg(g + cc + 1) + __ldg(b + cc + 1);
        v[j][0] = f0; v[j][1] = f1;
        st_hilo(sm, off, strideE, row, colbase + cc, K, f0, f1);
    }
}

__global__ void __launch_bounds__(128, 3)
main_kernel(const float* __restrict__ in_b, const float* __restrict__ out_b,
            const float* __restrict__ ln1_g, const float* __restrict__ ln1_b,
            const float* __restrict__ ff1_b, const float* __restrict__ ff2_b,
            const float* __restrict__ ln2_g, const float* __restrict__ ln2_b,
            const float* __restrict__ h1_b, const float* __restrict__ h2_w,
            const float* __restrict__ h2_b, float* __restrict__ out)
{
    extern __shared__ char sm[];
    const int tid = threadIdx.x, lane = tid & 31, w = tid >> 5;
    const int qr = lane >> 2, qc = lane & 3;
    const int rA = 16 * w + qr;               // token rows owned: rA, rA+8
    const int s0m = blockIdx.x << 5;          // first sample
    const uint32_t xt_u = smem_u32(sm + XT_OFF);
    const uint32_t ct_u = smem_u32(sm + CT_OFF);
    const uint32_t wb_u = smem_u32(sm + WB_OFF);
    const uint32_t wbuf[2] = { wb_u, wb_u + 17408u };

    // prefetch first weight chunk immediately
    stage_cp(wbuf[0], g_wbuf, 17408, tid);
    CP_COMMIT();

    // load x0 -> registers + XT tile
    float x_[2][8][2];
    {
        const float* x0p = g_x0 + (size_t)(blockIdx.x * 64) * 64;
        #pragma unroll
        for (int h = 0; h < 2; ++h) {
            int row = rA + 8 * h;
            const float* xp = x0p + (size_t)row * 64;
            #pragma unroll
            for (int j = 0; j < 8; ++j) {
                float2 f = __ldg(reinterpret_cast<const float2*>(xp + 8 * j + 2 * qc));
                x_[h][j][0] = f.x; x_[h][j][1] = f.y;
                st_hilo(sm, XT_OFF, 136, row, 8 * j + 2 * qc, 64, f.x, f.y);
            }
        }
        __syncwarp();
    }

    const uint32_t aXT = xt_u + (uint32_t)(16 * w) * 272u;
    const uint32_t aCT = ct_u + (uint32_t)(16 * w) * 272u;

    float q_[8][4];
    float wS[2][4], wO[2][4];
    float accF[8][4];
    int gidx = 0;

    for (int l = 0; l < 2; ++l) {
        for (int g = 0; g < 12; ++g) {
            CP_WAIT0();
            __syncthreads();
            if (gidx + 1 < 24) {
                stage_cp(wbuf[(gidx + 1) & 1], g_wbuf + (size_t)(gidx + 1) * 17408, 17408, tid);
                CP_COMMIT();
            }
            const uint32_t bb = wbuf[gidx & 1];

            if (g == 0) {
                // ---- q ----
                #pragma unroll
                for (int j = 0; j < 8; ++j) { q_[j][0] = q_[j][1] = q_[j][2] = q_[j][3] = 0.f; }
                gemm3<4>(q_, aXT, 272, bb, 272);
                const float* bq = in_b + l * 192;
                #pragma unroll
                for (int j = 0; j < 8; ++j) {
                    int c = 8 * j + 2 * qc;
                    float b0 = __ldg(bq + c), b1 = __ldg(bq + c + 1);
                    q_[j][0] += b0; q_[j][1] += b1; q_[j][2] += b0; q_[j][3] += b1;
                }
            } else if (g == 1) {
                // ---- k + scores + softmax ----
                float acc[8][4];
                #pragma unroll
                for (int j = 0; j < 8; ++j) { acc[j][0] = acc[j][1] = acc[j][2] = acc[j][3] = 0.f; }
                gemm3<4>(acc, aXT, 272, bb, 272);
                const float* bk = in_b + l * 192 + 64;
                #pragma unroll
                for (int j = 0; j < 8; ++j) {
                    int c = 8 * j + 2 * qc;
                    float b0 = __ldg(bk + c), b1 = __ldg(bk + c + 1);
                    acc[j][0] += b0; acc[j][1] += b1; acc[j][2] += b0; acc[j][3] += b1;
                }
                float sS[2][4], sO[2][4];
                #pragma unroll
                for (int h = 0; h < 4; ++h) {
                    int j0 = 2 * h, j1 = 2 * h + 1;
                    sS[0][h] = q_[j0][0] * acc[j0][0] + q_[j0][1] * acc[j0][1]
                             + q_[j1][0] * acc[j1][0] + q_[j1][1] * acc[j1][1];
                    sS[1][h] = q_[j0][2] * acc[j0][2] + q_[j0][3] * acc[j0][3]
                             + q_[j1][2] * acc[j1][2] + q_[j1][3] * acc[j1][3];
                    float k00 = __shfl_xor_sync(0xffffffffu, acc[j0][0], 4);
                    float k01 = __shfl_xor_sync(0xffffffffu, acc[j0][1], 4);
                    float k10 = __shfl_xor_sync(0xffffffffu, acc[j1][0], 4);
                    float k11 = __shfl_xor_sync(0xffffffffu, acc[j1][1], 4);
                    float k02 = __shfl_xor_sync(0xffffffffu, acc[j0][2], 4);
                    float k03 = __shfl_xor_sync(0xffffffffu, acc[j0][3], 4);
                    float k12 = __shfl_xor_sync(0xffffffffu, acc[j1][2], 4);
                    float k13 = __shfl_xor_sync(0xffffffffu, acc[j1][3], 4);
                    sO[0][h] = q_[j0][0] * k00 + q_[j0][1] * k01 + q_[j1][0] * k10 + q_[j1][1] * k11;
                    sO[1][h] = q_[j0][2] * k02 + q_[j0][3] * k03 + q_[j1][2] * k12 + q_[j1][3] * k13;
                }
                #pragma unroll
                for (int r = 0; r < 2; ++r)
                    #pragma unroll
                    for (int h = 0; h < 4; ++h) {
                        sS[r][h] += __shfl_xor_sync(0xffffffffu, sS[r][h], 1);
                        sS[r][h] += __shfl_xor_sync(0xffffffffu, sS[r][h], 2);
                        sO[r][h] += __shfl_xor_sync(0xffffffffu, sO[r][h], 1);
                        sO[r][h] += __shfl_xor_sync(0xffffffffu, sO[r][h], 2);
                        float a = sS[r][h] * 0.25f, o = sO[r][h] * 0.25f;
                        float m = fmaxf(a, o);
                        float ea = expf(a - m), eo = expf(o - m);
                        float inv = 1.f / (ea + eo);
                        wS[r][h] = ea * inv; wO[r][h] = eo * inv;
                    }
            } else if (g == 2) {
                // ---- v + ctx -> CT ----
                float acc[8][4];
                #pragma unroll
                for (int j = 0; j < 8; ++j) { acc[j][0] = acc[j][1] = acc[j][2] = acc[j][3] = 0.f; }
                gemm3<4>(acc, aXT, 272, bb, 272);
                const float* bv = in_b + l * 192 + 128;
                #pragma unroll
                for (int j = 0; j < 8; ++j) {
                    int c = 8 * j + 2 * qc;
                    float b0 = __ldg(bv + c), b1 = __ldg(bv + c + 1);
                    acc[j][0] += b0; acc[j][1] += b1; acc[j][2] += b0; acc[j][3] += b1;
                }
                #pragma unroll
                for (int j = 0; j < 8; ++j) {
                    int h = j >> 1, c = 8 * j + 2 * qc;
                    float p0 = __shfl_xor_sync(0xffffffffu, acc[j][0], 4);
                    float p1 = __shfl_xor_sync(0xffffffffu, acc[j][1], 4);
                    float p2 = __shfl_xor_sync(0xffffffffu, acc[j][2], 4);
                    float p3 = __shfl_xor_sync(0xffffffffu, acc[j][3], 4);
                    st_hilo(sm, CT_OFF, 136, rA, c, 64,
                            wS[0][h] * acc[j][0] + wO[0][h] * p0,
                            wS[0][h] * acc[j][1] + wO[0][h] * p1);
                    st_hilo(sm, CT_OFF, 136, rA + 8, c, 64,
                            wS[1][h] * acc[j][2] + wO[1][h] * p2,
                            wS[1][h] * acc[j][3] + wO[1][h] * p3);
                }
                __syncwarp();
            } else if (g == 3) {
                // ---- out-proj + residual + LN1 -> XT ----
                float acc[8][4];
                #pragma unroll
                for (int j = 0; j < 8; ++j) { acc[j][0] = acc[j][1] = acc[j][2] = acc[j][3] = 0.f; }
                gemm3<4>(acc, aCT, 272, bb, 272);
                const float* bo = out_b + l * 64;
                #pragma unroll
                for (int j = 0; j < 8; ++j) {
                    int c = 8 * j + 2 * qc;
                    float b0 = __ldg(bo + c), b1 = __ldg(bo + c + 1);
                    x_[0][j][0] += acc[j][0] + b0; x_[0][j][1] += acc[j][1] + b1;
                    x_[1][j][0] += acc[j][2] + b0; x_[1][j][1] += acc[j][3] + b1;
                }
                ln_reg(x_[0], ln1_g + l * 64, ln1_b + l * 64, sm, XT_OFF, 136, rA,     0, 64, qc);
                ln_reg(x_[1], ln1_g + l * 64, ln1_b + l * 64, sm, XT_OFF, 136, rA + 8, 0, 64, qc);
                __syncwarp();
            } else if (((g - 4) & 1) == 0) {
                // ---- ff1 chunk -> relu -> CT ----
                int c4 = (g - 4) >> 1;
                float acc[8][4];
                #pragma unroll
                for (int j = 0; j < 8; ++j) { acc[j][0] = acc[j][1] = acc[j][2] = acc[j][3] = 0.f; }
                gemm3<4>(acc, aXT, 272, bb, 272);
                const float* b1p = ff1_b + l * 256 + 64 * c4;
                #pragma unroll
                for (int j = 0; j < 8; ++j) {
                    int c = 8 * j + 2 * qc;
                    float b0 = __ldg(b1p + c), b1 = __ldg(b1p + c + 1);
                    st_hilo(sm, CT_OFF, 136, rA, c, 64,
                            fmaxf(acc[j][0] + b0, 0.f), fmaxf(acc[j][1] + b1, 0.f));
                    st_hilo(sm, CT_OFF, 136, rA + 8, c, 64,
                            fmaxf(acc[j][2] + b0, 0.f), fmaxf(acc[j][3] + b1, 0.f));
                }
                __syncwarp();
            } else {
                // ---- ff2 chunk accumulate ----
                int c4 = (g - 4) >> 1;
                if (c4 == 0) {
                    #pragma unroll
                    for (int j = 0; j < 8; ++j) { accF[j][0] = accF[j][1] = accF[j][2] = accF[j][3] = 0.f; }
                }
                gemm3<4>(accF, aCT, 272, bb, 272);
                if (c4 == 3) {
                    const float* b2 = ff2_b + l * 64;
                    #pragma unroll
                    for (int j = 0; j < 8; ++j) {
                        int c = 8 * j + 2 * qc;
                        float b0 = __ldg(b2 + c), b1 = __ldg(b2 + c + 1);
                        x_[0][j][0] += accF[j][0] + b0; x_[0][j][1] += accF[j][1] + b1;
                        x_[1][j][0] += accF[j][2] + b0; x_[1][j][1] += accF[j][3] + b1;
                    }
                    const float* g2 = ln2_g + l * 64;
                    const float* bL = ln2_b + l * 64;
                    if (l == 0) {
                        ln_reg(x_[0], g2, bL, sm, XT_OFF, 136, rA,     0, 64, qc);
                        ln_reg(x_[1], g2, bL, sm, XT_OFF, 136, rA + 8, 0, 64, qc);
                    } else {
                        // head layout: sample row = token>>1, col half = 64*(token&1)
                        ln_reg(x_[0], g2, bL, sm, XT_OFF, 264, rA >> 1,       64 * (rA & 1),       128, qc);
                        ln_reg(x_[1], g2, bL, sm, XT_OFF, 264, (rA + 8) >> 1, 64 * ((rA + 8) & 1), 128, qc);
                    }
                    __syncwarp();
                }
            }
            ++gidx;
        }
    }

    // ================= head =================
    CP_WAIT0();
    __syncthreads();                        // XT head tile complete; WB free
    stage_cp(wb_u, g_wbuf + 24 * 17408, 33792, tid);
    CP_COMMIT(); CP_WAIT0();
    __syncthreads();

    if (w < 2) {
        float acc[8][4];
        #pragma unroll
        for (int j = 0; j < 8; ++j) { acc[j][0] = acc[j][1] = acc[j][2] = acc[j][3] = 0.f; }
        gemm3<8>(acc, xt_u + (uint32_t)(16 * w) * 528u, 528, wb_u, 528);
        float pA = 0.f, pB = 0.f;
        #pragma unroll
        for (int j = 0; j < 8; ++j) {
            int c = 8 * j + 2 * qc;
            float b0 = __ldg(h1_b + c), b1 = __ldg(h1_b + c + 1);
            float w0 = __ldg(h2_w + c), w1 = __ldg(h2_w + c + 1);
            pA += fmaxf(acc[j][0] + b0, 0.f) * w0 + fmaxf(acc[j][1] + b1, 0.f) * w1;
            pB += fmaxf(acc[j][2] + b0, 0.f) * w0 + fmaxf(acc[j][3] + b1, 0.f) * w1;
        }
        pA += __shfl_xor_sync(0xffffffffu, pA, 1);
        pA += __shfl_xor_sync(0xffffffffu, pA, 2);
        pB += __shfl_xor_sync(0xffffffffu, pB, 1);
        pB += __shfl_xor_sync(0xffffffffu, pB, 2);
        if (qc == 0) {
            float hb = __ldg(h2_b);
            out[s0m + 16 * w + qr]     = pA + hb;
            out[s0m + 16 * w + qr + 8] = pB + hb;
        }
    }
}

// =====================================================================================
extern "C" void kernel_launch(void* const* d_in, const int* in_sizes, int n_in,
                              void* d_out, int out_size)
{
    const int*   user_idx      = (const int*)  d_in[0];
    const int*   item_idx      = (const int*)  d_in[1];
    const float* user_features = (const float*)d_in[2];
    const float* item_features = (const float*)d_in[3];
    const float* user_table    = (const float*)d_in[4];
    const float* item_table    = (const float*)d_in[5];
    const float* upw           = (const float*)d_in[6];
    const float* upb           = (const float*)d_in[7];
    const float* ipw           = (const float*)d_in[8];
    const float* ipb           = (const float*)d_in[9];
    const float* pe            = (const float*)d_in[10];
    const float* in_w          = (const float*)d_in[11];
    const float* in_b          = (const float*)d_in[12];
    const float* out_w         = (const float*)d_in[13];
    const float* out_b         = (const float*)d_in[14];
    const float* ln1_g         = (const float*)d_in[15];
    const float* ln1_b         = (const float*)d_in[16];
    const float* ff1_w         = (const float*)d_in[17];
    const float* ff1_b         = (const float*)d_in[18];
    const float* ff2_w         = (const float*)d_in[19];
    const float* ff2_b         = (const float*)d_in[20];
    const float* ln2_g         = (const float*)d_in[21];
    const float* ln2_b         = (const float*)d_in[22];
    const float* h1_w          = (const float*)d_in[23];
    const float* h1_b          = (const float*)d_in[24];
    const float* h2_w          = (const float*)d_in[25];
    const float* h2_b          = (const float*)d_in[26];
    float* out = (float*)d_out;

    const int B = in_sizes[0];

    static bool attr_set = false;
    if (!attr_set) {
        cudaFuncSetAttribute(embed_kernel, cudaFuncAttributeMaxDynamicSharedMemorySize, EB_SMEM);
        cudaFuncSetAttribute(main_kernel,  cudaFuncAttributeMaxDynamicSharedMemorySize, MAIN_SMEM);
        attr_set = true;
    }

    conv_w_kernel<<<25, 256>>>(in_w, out_w, ff1_w, ff2_w, h1_w);
    embed_kernel<<<B / 64, 256, EB_SMEM>>>(user_idx, item_idx, user_features, item_features,
                                           user_table, item_table, upw, upb, ipw, ipb, pe);
    main_kernel<<<B / 32, 128, MAIN_SMEM>>>(in_b, out_b, ln1_g, ln1_b, ff1_b, ff2_b,
                                            ln2_g, ln2_b, h1_b, h2_w, h2_b, out);
}